// round 9
// baseline (speedup 1.0000x reference)
#include <cuda_runtime.h>
#include <cuda_fp16.h>

#define NN 100000
#define NE 1250000
#define D  64
#define EF 13
#define SCAN_B 1024

#define FMA2(d, a, b) \
    asm("fma.rn.f32x2 %0, %1, %2, %0;" : "+l"(d) : "l"(a), "l"(b))

// ---------------- scratch (device globals; no allocation allowed) ----------------
__device__ float g_sm[EF];
__device__ int   g_is64;
__device__ int   g_rows[NE];
__device__ int   g_cols[NE];
__device__ float g_ew[NE];
__device__ float g_deg[NN];
__device__ float g_dinv[NN];
__device__ float g_dsq[NN];
__device__ int   g_cnt[NN];       // in-degree (edge count per dest)
__device__ int   g_start[NN];     // CSR offsets
__device__ int   g_cursor[NN];    // build cursors
__device__ int   g_bsum[128];     // scan partials
__device__ __align__(16) uint2 g_edge[NE];       // packed (row, norm) sorted by col
__device__ __align__(16) __half g_hh[NN * D];    // GEMM output, fp16 (gather payload)
__device__ __align__(16) float g_bufA[NN * D];   // x1
__device__ __align__(16) float g_bufB[NN * D];   // x2
__device__ float g_S[3 * D];      // pool numerators
__device__ float g_Z[3];          // pool denominators

// ----- init: softmax(aaaaa) + dtype sniff (1 thread), deg/cnt init (grid-wide) ----
__global__ void k_init(const float* __restrict__ aaaaa,
                       const int* __restrict__ ei_raw, int n) {
    int i = blockIdx.x * blockDim.x + threadIdx.x;
    if (i < 3 * D) g_S[i] = 0.0f;
    if (i < 3)     g_Z[i] = 0.0f;
    if (i < n) { g_deg[i] = 1.0f; g_cnt[i] = 0; }
    if (i == 0) {
        float v[EF];
        float m = -1e30f;
        for (int j = 0; j < EF; j++) { v[j] = aaaaa[j]; m = fmaxf(m, v[j]); }
        float s = 0.0f;
        for (int j = 0; j < EF; j++) { v[j] = expf(v[j] - m); s += v[j]; }
        for (int j = 0; j < EF; j++) g_sm[j] = v[j] / s;
        // dtype sniff: int64 indices have zero high words
        int is64 = 1;
        for (int k = 0; k < 64; k++)
            if (ei_raw[2 * k + 1] != 0) { is64 = 0; break; }
        g_is64 = is64;
    }
}

// ---- decode edge_index + edge weight + per-dest count/deg (single edge pass) ----
__global__ void k_decode_ew(const void* __restrict__ ei,
                            const float* __restrict__ ea, int E) {
    int e = blockIdx.x * blockDim.x + threadIdx.x;
    if (e >= E) return;
    int r, c;
    if (g_is64) {
        const long long* p = (const long long*)ei;
        r = (int)p[e];
        c = (int)p[E + e];
    } else {
        const int* p = (const int*)ei;
        r = p[e];
        c = p[E + e];
    }
    g_rows[e] = r;
    g_cols[e] = c;

    const float* row = ea + (long long)e * EF;
    float s = 0.0f;
#pragma unroll
    for (int j = 0; j < EF; j++) s += __ldg(row + j) * g_sm[j];
    g_ew[e] = s;
    atomicAdd(&g_deg[c], s);
    atomicAdd(&g_cnt[c], 1);
}

// -------- fused: deg^{-1/2} (elementwise) + per-block sums of g_cnt ---------------
__global__ void k_scanA(int n) {
    __shared__ int sm[SCAN_B];
    int i = blockIdx.x * SCAN_B + threadIdx.x;
    if (i < n) {
        float di = rsqrtf(g_deg[i]);   // deg >= 1 always
        g_dinv[i] = di;
        g_dsq[i] = di * di;
    }
    sm[threadIdx.x] = (i < n) ? g_cnt[i] : 0;
    __syncthreads();
    for (int off = SCAN_B / 2; off > 0; off >>= 1) {
        if (threadIdx.x < off) sm[threadIdx.x] += sm[threadIdx.x + off];
        __syncthreads();
    }
    if (threadIdx.x == 0) g_bsum[blockIdx.x] = sm[0];
}

// ---- scan stage C (with inlined block-offset reduce): CSR offsets + cursors ------
__global__ void k_scanC(int n, int nblk) {
    __shared__ int sm[SCAN_B];
    __shared__ int sboff;
    // block offset = sum of bsum[0 .. blockIdx-1]
    int partial = (threadIdx.x < blockIdx.x && threadIdx.x < nblk)
                  ? g_bsum[threadIdx.x] : 0;
    sm[threadIdx.x] = partial;
    __syncthreads();
    for (int off = SCAN_B / 2; off > 0; off >>= 1) {
        if (threadIdx.x < off) sm[threadIdx.x] += sm[threadIdx.x + off];
        __syncthreads();
    }
    if (threadIdx.x == 0) sboff = sm[0];
    __syncthreads();

    int i = blockIdx.x * SCAN_B + threadIdx.x;
    int v = (i < n) ? g_cnt[i] : 0;
    sm[threadIdx.x] = v;
    __syncthreads();
    for (int off = 1; off < SCAN_B; off <<= 1) {
        int t = (threadIdx.x >= off) ? sm[threadIdx.x - off] : 0;
        __syncthreads();
        sm[threadIdx.x] += t;
        __syncthreads();
    }
    if (i < n) {
        int st = sboff + sm[threadIdx.x] - v;  // exclusive
        g_start[i] = st;
        g_cursor[i] = st;
    }
}

// ---------------- CSR build: pack (row, norm) sorted by destination ---------------
__global__ void k_build(int E) {
    int e = blockIdx.x * blockDim.x + threadIdx.x;
    if (e >= E) return;
    int r = g_rows[e];
    int c = g_cols[e];
    float nrm = g_dinv[r] * g_ew[e] * g_dinv[c];
    int pos = atomicAdd(&g_cursor[c], 1);
    g_edge[pos] = make_uint2((unsigned)r, __float_as_uint(nrm));
}

// ------ GEMM: h = x @ W  (thread per row, W in smem, packed f32x2 FMA) ------------
__global__ void k_gemm(const float* __restrict__ xext, int sel,
                       const float* __restrict__ W, int n) {
    __shared__ __align__(16) float Ws[D * D];
    for (int i = threadIdx.x; i < D * D; i += blockDim.x) Ws[i] = W[i];
    __syncthreads();

    const float* x = (sel == 0) ? xext : ((sel == 1) ? g_bufA : g_bufB);
    int row = blockIdx.x * blockDim.x + threadIdx.x;
    if (row >= n) return;

    const float4* xr = (const float4*)(x + (long long)row * D);
    unsigned long long acc[32];   // 32 packed f32x2 = 64 output cols
#pragma unroll
    for (int c = 0; c < 32; c++) acc[c] = 0ull;

#pragma unroll 1
    for (int k4 = 0; k4 < 16; k4++) {
        float4 xv = xr[k4];
        float xa[4] = {xv.x, xv.y, xv.z, xv.w};
#pragma unroll
        for (int kk = 0; kk < 4; kk++) {
            unsigned long long xkk;
            asm("mov.b64 %0, {%1, %1};" : "=l"(xkk) : "f"(xa[kk]));
            const ulonglong2* w4 = (const ulonglong2*)&Ws[(k4 * 4 + kk) * D];
#pragma unroll
            for (int c2 = 0; c2 < 16; c2++) {
                ulonglong2 wv = w4[c2];
                FMA2(acc[2 * c2],     xkk, wv.x);
                FMA2(acc[2 * c2 + 1], xkk, wv.y);
            }
        }
    }
    __half2* ho = (__half2*)(g_hh + (long long)row * D);
#pragma unroll
    for (int c = 0; c < 32; c++) {
        float lo, hi;
        asm("mov.b64 {%0, %1}, %2;" : "=f"(lo), "=f"(hi) : "l"(acc[c]));
        ho[c] = __float22half2_rn(make_float2(lo, hi));
    }
}

// ------ fused CSR aggregate (+self loop, fp16 payload) + bias/relu + pool ---------
// warp per node (grid-stride); lane owns features (2l, 2l+1).
// Cross-node software pipeline: next node's metadata + first record block are
// fetched while the current node's payloads / pool math are in flight.
__global__ void __launch_bounds__(256) k_aggpool(
        int sel_out, const float* __restrict__ b,
        const float* __restrict__ wg, const float* __restrict__ bg,
        int layer, int n) {
    __shared__ float ps0[8][32];
    __shared__ float ps1[8][32];
    __shared__ float pz[8];
    float* xo = (sel_out == 1) ? g_bufA : ((sel_out == 2) ? g_bufB : 0);
    int lane = threadIdx.x & 31;
    int wlocal = threadIdx.x >> 5;
    int warp = (blockIdx.x * blockDim.x + threadIdx.x) >> 5;
    int nwarps = (gridDim.x * blockDim.x) >> 5;

    float wg0 = wg[2 * lane], wg1 = wg[2 * lane + 1];
    float b0 = b[2 * lane],  b1 = b[2 * lane + 1];
    float bgv = bg[0];

    const __half2* hp = (const __half2*)g_hh;   // element index = row*32 + lane

    float s0 = 0.f, s1 = 0.f, z = 0.f;

    // pipeline prologue: node `warp`
    int i = warp;
    float ds_c = 0.f;
    int j0_c = 0, cnt_c = 0;
    uint2 rec_c = make_uint2(0u, 0u);
    if (i < n) {
        ds_c = g_dsq[i];
        j0_c = g_start[i];
        cnt_c = g_cnt[i];
        if (lane < min(cnt_c, 32)) rec_c = g_edge[j0_c + lane];
    }

    while (i < n) {
        int inext = i + nwarps;
        // issue next node's metadata loads early (independent of current work)
        float ds_n = 0.f;
        int j0_n = 0, cnt_n = 0;
        if (inext < n) {
            ds_n = g_dsq[inext];
            j0_n = g_start[inext];
            cnt_n = g_cnt[inext];
        }

        // current node: self loop + first record block (already in registers)
        float2 hv = __half22float2(hp[(long long)i * 32 + lane]);
        float a0 = ds_c * hv.x;
        float a1 = ds_c * hv.y;

        int m = min(cnt_c, 32);
        int t = 0;
        for (; t + 1 < m; t += 2) {
            unsigned rx0 = __shfl_sync(0xffffffffu, rec_c.x, t);
            unsigned ry0 = __shfl_sync(0xffffffffu, rec_c.y, t);
            unsigned rx1 = __shfl_sync(0xffffffffu, rec_c.x, t + 1);
            unsigned ry1 = __shfl_sync(0xffffffffu, rec_c.y, t + 1);
            float2 f0 = __half22float2(hp[(long long)rx0 * 32 + lane]);
            float2 f1 = __half22float2(hp[(long long)rx1 * 32 + lane]);
            float n0 = __uint_as_float(ry0);
            float n1 = __uint_as_float(ry1);
            a0 = fmaf(n0, f0.x, a0); a1 = fmaf(n0, f0.y, a1);
            a0 = fmaf(n1, f1.x, a0); a1 = fmaf(n1, f1.y, a1);
        }
        if (t < m) {
            unsigned rx0 = __shfl_sync(0xffffffffu, rec_c.x, t);
            unsigned ry0 = __shfl_sync(0xffffffffu, rec_c.y, t);
            float2 f0 = __half22float2(hp[(long long)rx0 * 32 + lane]);
            float n0 = __uint_as_float(ry0);
            a0 = fmaf(n0, f0.x, a0); a1 = fmaf(n0, f0.y, a1);
        }
        // rare extra blocks (deg > 32)
        for (int base = 32; base < cnt_c; base += 32) {
            int mm = min(32, cnt_c - base);
            uint2 rec = make_uint2(0u, 0u);
            if (lane < mm) rec = g_edge[j0_c + base + lane];
            int tt = 0;
            for (; tt < mm; tt++) {
                unsigned rx0 = __shfl_sync(0xffffffffu, rec.x, tt);
                unsigned ry0 = __shfl_sync(0xffffffffu, rec.y, tt);
                float2 f0 = __half22float2(hp[(long long)rx0 * 32 + lane]);
                float n0 = __uint_as_float(ry0);
                a0 = fmaf(n0, f0.x, a0); a1 = fmaf(n0, f0.y, a1);
            }
        }

        // prefetch next node's first record block (metadata has arrived by now);
        // overlaps with the pool math below.
        uint2 rec_n = make_uint2(0u, 0u);
        if (inext < n && lane < min(cnt_n, 32)) rec_n = g_edge[j0_n + lane];

        // finalize + pool for current node
        float v0 = fmaxf(a0 + b0, 0.f);
        float v1 = fmaxf(a1 + b1, 0.f);
        if (xo) {
            ((float2*)(xo + (long long)i * D))[lane] = make_float2(v0, v1);
        }
        float dot = v0 * wg0 + v1 * wg1;
#pragma unroll
        for (int off = 16; off > 0; off >>= 1)
            dot += __shfl_xor_sync(0xffffffffu, dot, off);
        float sg = 1.0f / (1.0f + expf(-(dot + bgv)));  // sigmoid gate
        float w = expf(sg);                             // softmax numerator
        s0 += w * v0;
        s1 += w * v1;
        if (lane == 0) z += w;

        // rotate pipeline state
        i = inext;
        ds_c = ds_n; j0_c = j0_n; cnt_c = cnt_n; rec_c = rec_n;
    }

    // block-level reduction of pool partials, one atomic set per block
    ps0[wlocal][lane] = s0;
    ps1[wlocal][lane] = s1;
    if (lane == 0) pz[wlocal] = z;
    __syncthreads();
    if (wlocal == 0) {
        float t0 = 0.f, t1 = 0.f, tz = 0.f;
#pragma unroll
        for (int w8 = 0; w8 < 8; w8++) {
            t0 += ps0[w8][lane];
            t1 += ps1[w8][lane];
            if (lane == 0) tz += pz[w8];
        }
        atomicAdd(&g_S[layer * D + 2 * lane], t0);
        atomicAdd(&g_S[layer * D + 2 * lane + 1], t1);
        if (lane == 0) atomicAdd(&g_Z[layer], tz);
    }
}

// ---------------- final divide ----------------------------------------------------
__global__ void k_out(float* __restrict__ out) {
    int t = threadIdx.x;
    if (t < 3 * D) out[t] = g_S[t] / g_Z[t / D];
}

// ---------------- launch ----------------------------------------------------------
extern "C" void kernel_launch(void* const* d_in, const int* in_sizes, int n_in,
                              void* d_out, int out_size) {
    const float* x     = (const float*)d_in[0];
    const void*  ei    = d_in[1];
    const float* ea    = (const float*)d_in[2];
    const float* aaaaa = (const float*)d_in[3];
    const float* W[3]  = {(const float*)d_in[4], (const float*)d_in[6], (const float*)d_in[8]};
    const float* b[3]  = {(const float*)d_in[5], (const float*)d_in[7], (const float*)d_in[9]};
    const float* wg[3] = {(const float*)d_in[10], (const float*)d_in[12], (const float*)d_in[14]};
    const float* bg[3] = {(const float*)d_in[11], (const float*)d_in[13], (const float*)d_in[15]};
    float* out = (float*)d_out;

    int N = in_sizes[0] / D;     // 100000
    int E = in_sizes[2] / EF;    // 1250000
    int nblk = (N + SCAN_B - 1) / SCAN_B;

    k_init<<<(N + 255) / 256, 256>>>(aaaaa, (const int*)ei, N);
    k_decode_ew<<<(E + 255) / 256, 256>>>(ei, ea, E);
    k_scanA<<<nblk, SCAN_B>>>(N);
    k_scanC<<<nblk, SCAN_B>>>(N, nblk);
    k_build<<<(E + 255) / 256, 256>>>(E);

    // layer 1: x(ext) -> h -> bufA, pool 0
    k_gemm<<<(N + 127) / 128, 128>>>(x, 0, W[0], N);
    k_aggpool<<<1024, 256>>>(1, b[0], wg[0], bg[0], 0, N);
    // layer 2: bufA -> h -> bufB, pool 1
    k_gemm<<<(N + 127) / 128, 128>>>(x, 1, W[1], N);
    k_aggpool<<<1024, 256>>>(2, b[1], wg[1], bg[1], 1, N);
    // layer 3: bufB -> h -> (pool only), pool 2
    k_gemm<<<(N + 127) / 128, 128>>>(x, 2, W[2], N);
    k_aggpool<<<1024, 256>>>(0, b[2], wg[2], bg[2], 2, N);

    k_out<<<1, 192>>>(out);
}

// round 10
// speedup vs baseline: 1.1378x; 1.1378x over previous
#include <cuda_runtime.h>
#include <cuda_fp16.h>

#define NN 100000
#define NE 1250000
#define D  64
#define EF 13
#define SCAN_B 1024

#define FMA2(d, a, b) \
    asm("fma.rn.f32x2 %0, %1, %2, %0;" : "+l"(d) : "l"(a), "l"(b))

// ---------------- scratch (device globals; no allocation allowed) ----------------
__device__ float g_sm[EF];
__device__ int   g_is64;
__device__ int   g_rows[NE];
__device__ int   g_cols[NE];
__device__ float g_ew[NE];
__device__ float g_deg[NN];
__device__ float g_dinv[NN];
__device__ float g_dsq[NN];
__device__ int   g_cnt[NN];       // in-degree (edge count per dest)
__device__ int   g_start[NN];     // CSR offsets
__device__ int   g_cursor[NN];    // build cursors
__device__ int   g_bsum[128];     // scan partials
__device__ __align__(16) uint2 g_edge[NE];       // packed (row, norm) sorted by col
__device__ __align__(16) __half g_hh[NN * D];    // GEMM output, fp16 (gather payload)
__device__ __align__(16) float g_bufA[NN * D];   // x1
__device__ __align__(16) float g_bufB[NN * D];   // x2
__device__ float g_S[3 * D];      // pool numerators
__device__ float g_Z[3];          // pool denominators

// ----- init: softmax(aaaaa) + dtype sniff (1 thread), deg/cnt init (grid-wide) ----
__global__ void k_init(const float* __restrict__ aaaaa,
                       const int* __restrict__ ei_raw, int n) {
    int i = blockIdx.x * blockDim.x + threadIdx.x;
    if (i < 3 * D) g_S[i] = 0.0f;
    if (i < 3)     g_Z[i] = 0.0f;
    if (i < n) { g_deg[i] = 1.0f; g_cnt[i] = 0; }
    if (i == 0) {
        float v[EF];
        float m = -1e30f;
        for (int j = 0; j < EF; j++) { v[j] = aaaaa[j]; m = fmaxf(m, v[j]); }
        float s = 0.0f;
        for (int j = 0; j < EF; j++) { v[j] = expf(v[j] - m); s += v[j]; }
        for (int j = 0; j < EF; j++) g_sm[j] = v[j] / s;
        // dtype sniff: int64 indices have zero high words
        int is64 = 1;
        for (int k = 0; k < 64; k++)
            if (ei_raw[2 * k + 1] != 0) { is64 = 0; break; }
        g_is64 = is64;
    }
}

// ---- decode edge_index + edge weight + per-dest count/deg (single edge pass) ----
__global__ void k_decode_ew(const void* __restrict__ ei,
                            const float* __restrict__ ea, int E) {
    int e = blockIdx.x * blockDim.x + threadIdx.x;
    if (e >= E) return;
    int r, c;
    if (g_is64) {
        const long long* p = (const long long*)ei;
        r = (int)p[e];
        c = (int)p[E + e];
    } else {
        const int* p = (const int*)ei;
        r = p[e];
        c = p[E + e];
    }
    g_rows[e] = r;
    g_cols[e] = c;

    const float* row = ea + (long long)e * EF;
    float s = 0.0f;
#pragma unroll
    for (int j = 0; j < EF; j++) s += __ldg(row + j) * g_sm[j];
    g_ew[e] = s;
    atomicAdd(&g_deg[c], s);
    atomicAdd(&g_cnt[c], 1);
}

// -------- fused: deg^{-1/2} (elementwise) + per-block sums of g_cnt ---------------
__global__ void k_scanA(int n) {
    __shared__ int sm[SCAN_B];
    int i = blockIdx.x * SCAN_B + threadIdx.x;
    if (i < n) {
        float di = rsqrtf(g_deg[i]);   // deg >= 1 always
        g_dinv[i] = di;
        g_dsq[i] = di * di;
    }
    sm[threadIdx.x] = (i < n) ? g_cnt[i] : 0;
    __syncthreads();
    for (int off = SCAN_B / 2; off > 0; off >>= 1) {
        if (threadIdx.x < off) sm[threadIdx.x] += sm[threadIdx.x + off];
        __syncthreads();
    }
    if (threadIdx.x == 0) g_bsum[blockIdx.x] = sm[0];
}

// ---- scan stage C (with inlined block-offset reduce): CSR offsets + cursors ------
__global__ void k_scanC(int n, int nblk) {
    __shared__ int sm[SCAN_B];
    __shared__ int sboff;
    // block offset = sum of bsum[0 .. blockIdx-1]
    int partial = (threadIdx.x < blockIdx.x && threadIdx.x < nblk)
                  ? g_bsum[threadIdx.x] : 0;
    sm[threadIdx.x] = partial;
    __syncthreads();
    for (int off = SCAN_B / 2; off > 0; off >>= 1) {
        if (threadIdx.x < off) sm[threadIdx.x] += sm[threadIdx.x + off];
        __syncthreads();
    }
    if (threadIdx.x == 0) sboff = sm[0];
    __syncthreads();

    int i = blockIdx.x * SCAN_B + threadIdx.x;
    int v = (i < n) ? g_cnt[i] : 0;
    sm[threadIdx.x] = v;
    __syncthreads();
    for (int off = 1; off < SCAN_B; off <<= 1) {
        int t = (threadIdx.x >= off) ? sm[threadIdx.x - off] : 0;
        __syncthreads();
        sm[threadIdx.x] += t;
        __syncthreads();
    }
    if (i < n) {
        int st = sboff + sm[threadIdx.x] - v;  // exclusive
        g_start[i] = st;
        g_cursor[i] = st;
    }
}

// ---------------- CSR build: pack (row, norm) sorted by destination ---------------
__global__ void k_build(int E) {
    int e = blockIdx.x * blockDim.x + threadIdx.x;
    if (e >= E) return;
    int r = g_rows[e];
    int c = g_cols[e];
    float nrm = g_dinv[r] * g_ew[e] * g_dinv[c];
    int pos = atomicAdd(&g_cursor[c], 1);
    g_edge[pos] = make_uint2((unsigned)r, __float_as_uint(nrm));
}

// --- GEMM: h = x @ W (thread per row, W in smem, packed f32x2 FMA, full unroll) ---
__global__ void k_gemm(const float* __restrict__ xext, int sel,
                       const float* __restrict__ W, int n) {
    __shared__ __align__(16) float Ws[D * D];
    for (int i = threadIdx.x; i < D * D; i += blockDim.x) Ws[i] = W[i];
    __syncthreads();

    const float* x = (sel == 0) ? xext : ((sel == 1) ? g_bufA : g_bufB);
    int row = blockIdx.x * blockDim.x + threadIdx.x;
    if (row >= n) return;

    const float4* xr = (const float4*)(x + (long long)row * D);
    // load the full x row up front: 16 independent float4 loads in flight
    float4 xv[16];
#pragma unroll
    for (int k4 = 0; k4 < 16; k4++) xv[k4] = xr[k4];

    unsigned long long acc[32];   // 32 packed f32x2 = 64 output cols
#pragma unroll
    for (int c = 0; c < 32; c++) acc[c] = 0ull;

#pragma unroll
    for (int k4 = 0; k4 < 16; k4++) {
        float xa[4] = {xv[k4].x, xv[k4].y, xv[k4].z, xv[k4].w};
#pragma unroll
        for (int kk = 0; kk < 4; kk++) {
            unsigned long long xkk;
            asm("mov.b64 %0, {%1, %1};" : "=l"(xkk) : "f"(xa[kk]));
            const ulonglong2* w4 = (const ulonglong2*)&Ws[(k4 * 4 + kk) * D];
#pragma unroll
            for (int c2 = 0; c2 < 16; c2++) {
                ulonglong2 wv = w4[c2];
                FMA2(acc[2 * c2],     xkk, wv.x);
                FMA2(acc[2 * c2 + 1], xkk, wv.y);
            }
        }
    }
    __half2* ho = (__half2*)(g_hh + (long long)row * D);
#pragma unroll
    for (int c = 0; c < 32; c++) {
        float lo, hi;
        asm("mov.b64 {%0, %1}, %2;" : "=f"(lo), "=f"(hi) : "l"(acc[c]));
        ho[c] = __float22half2_rn(make_float2(lo, hi));
    }
}

// ------ fused CSR aggregate (+self loop, fp16 payload) + bias/relu + pool ---------
// warp per node (grid-stride); lane owns features (2l, 2l+1).
// Records loaded lane-parallel (1 coalesced load per <=32 edges), broadcast via
// shfl -> payload loads depend only on registers -> MLP ~= node degree.
__global__ void __launch_bounds__(256) k_aggpool(
        int sel_out, const float* __restrict__ b,
        const float* __restrict__ wg, const float* __restrict__ bg,
        int layer, int n) {
    __shared__ float ps0[8][32];
    __shared__ float ps1[8][32];
    __shared__ float pz[8];
    float* xo = (sel_out == 1) ? g_bufA : ((sel_out == 2) ? g_bufB : 0);
    int lane = threadIdx.x & 31;
    int wlocal = threadIdx.x >> 5;
    int warp = (blockIdx.x * blockDim.x + threadIdx.x) >> 5;
    int nwarps = (gridDim.x * blockDim.x) >> 5;

    float wg0 = wg[2 * lane], wg1 = wg[2 * lane + 1];
    float b0 = b[2 * lane],  b1 = b[2 * lane + 1];
    float bgv = bg[0];

    const __half2* hp = (const __half2*)g_hh;   // element index = row*32 + lane

    float s0 = 0.f, s1 = 0.f, z = 0.f;

    for (int i = warp; i < n; i += nwarps) {
        float ds = g_dsq[i];
        float2 hv = __half22float2(hp[(long long)i * 32 + lane]);
        float a0 = ds * hv.x;
        float a1 = ds * hv.y;

        int j0 = g_start[i];
        int cnt = g_cnt[i];

        for (int base = 0; base < cnt; base += 32) {
            int m = min(32, cnt - base);
            // lane-parallel record fetch: one coalesced transaction for <=32 edges
            uint2 rec = make_uint2(0u, 0u);
            if (lane < m) rec = g_edge[j0 + base + lane];

            int t = 0;
            for (; t + 1 < m; t += 2) {
                unsigned rx0 = __shfl_sync(0xffffffffu, rec.x, t);
                unsigned ry0 = __shfl_sync(0xffffffffu, rec.y, t);
                unsigned rx1 = __shfl_sync(0xffffffffu, rec.x, t + 1);
                unsigned ry1 = __shfl_sync(0xffffffffu, rec.y, t + 1);
                float2 f0 = __half22float2(hp[(long long)rx0 * 32 + lane]);
                float2 f1 = __half22float2(hp[(long long)rx1 * 32 + lane]);
                float n0 = __uint_as_float(ry0);
                float n1 = __uint_as_float(ry1);
                a0 = fmaf(n0, f0.x, a0); a1 = fmaf(n0, f0.y, a1);
                a0 = fmaf(n1, f1.x, a0); a1 = fmaf(n1, f1.y, a1);
            }
            if (t < m) {
                unsigned rx0 = __shfl_sync(0xffffffffu, rec.x, t);
                unsigned ry0 = __shfl_sync(0xffffffffu, rec.y, t);
                float2 f0 = __half22float2(hp[(long long)rx0 * 32 + lane]);
                float n0 = __uint_as_float(ry0);
                a0 = fmaf(n0, f0.x, a0); a1 = fmaf(n0, f0.y, a1);
            }
        }

        float v0 = fmaxf(a0 + b0, 0.f);
        float v1 = fmaxf(a1 + b1, 0.f);
        if (xo) {
            // coalesced float2 store: features (2l, 2l+1)
            ((float2*)(xo + (long long)i * D))[lane] = make_float2(v0, v1);
        }

        float dot = v0 * wg0 + v1 * wg1;
#pragma unroll
        for (int off = 16; off > 0; off >>= 1)
            dot += __shfl_xor_sync(0xffffffffu, dot, off);
        float sg = 1.0f / (1.0f + expf(-(dot + bgv)));  // sigmoid gate
        float w = expf(sg);                             // softmax numerator
        s0 += w * v0;
        s1 += w * v1;
        if (lane == 0) z += w;
    }

    // block-level reduction of pool partials, one atomic set per block
    ps0[wlocal][lane] = s0;
    ps1[wlocal][lane] = s1;
    if (lane == 0) pz[wlocal] = z;
    __syncthreads();
    if (wlocal == 0) {
        float t0 = 0.f, t1 = 0.f, tz = 0.f;
#pragma unroll
        for (int w8 = 0; w8 < 8; w8++) {
            t0 += ps0[w8][lane];
            t1 += ps1[w8][lane];
            if (lane == 0) tz += pz[w8];
        }
        atomicAdd(&g_S[layer * D + 2 * lane], t0);
        atomicAdd(&g_S[layer * D + 2 * lane + 1], t1);
        if (lane == 0) atomicAdd(&g_Z[layer], tz);
    }
}

// ---------------- final divide ----------------------------------------------------
__global__ void k_out(float* __restrict__ out) {
    int t = threadIdx.x;
    if (t < 3 * D) out[t] = g_S[t] / g_Z[t / D];
}

// ---------------- launch ----------------------------------------------------------
extern "C" void kernel_launch(void* const* d_in, const int* in_sizes, int n_in,
                              void* d_out, int out_size) {
    const float* x     = (const float*)d_in[0];
    const void*  ei    = d_in[1];
    const float* ea    = (const float*)d_in[2];
    const float* aaaaa = (const float*)d_in[3];
    const float* W[3]  = {(const float*)d_in[4], (const float*)d_in[6], (const float*)d_in[8]};
    const float* b[3]  = {(const float*)d_in[5], (const float*)d_in[7], (const float*)d_in[9]};
    const float* wg[3] = {(const float*)d_in[10], (const float*)d_in[12], (const float*)d_in[14]};
    const float* bg[3] = {(const float*)d_in[11], (const float*)d_in[13], (const float*)d_in[15]};
    float* out = (float*)d_out;

    int N = in_sizes[0] / D;     // 100000
    int E = in_sizes[2] / EF;    // 1250000
    int nblk = (N + SCAN_B - 1) / SCAN_B;

    k_init<<<(N + 255) / 256, 256>>>(aaaaa, (const int*)ei, N);
    k_decode_ew<<<(E + 255) / 256, 256>>>(ei, ea, E);
    k_scanA<<<nblk, SCAN_B>>>(N);
    k_scanC<<<nblk, SCAN_B>>>(N, nblk);
    k_build<<<(E + 255) / 256, 256>>>(E);

    // layer 1: x(ext) -> h -> bufA, pool 0
    k_gemm<<<(N + 127) / 128, 128>>>(x, 0, W[0], N);
    k_aggpool<<<1024, 256>>>(1, b[0], wg[0], bg[0], 0, N);
    // layer 2: bufA -> h -> bufB, pool 1
    k_gemm<<<(N + 127) / 128, 128>>>(x, 1, W[1], N);
    k_aggpool<<<1024, 256>>>(2, b[1], wg[1], bg[1], 1, N);
    // layer 3: bufB -> h -> (pool only), pool 2
    k_gemm<<<(N + 127) / 128, 128>>>(x, 2, W[2], N);
    k_aggpool<<<1024, 256>>>(0, b[2], wg[2], bg[2], 2, N);

    k_out<<<1, 192>>>(out);
}